// round 1
// baseline (speedup 1.0000x reference)
#include <cuda_runtime.h>

#define NN 100000
#define NE 1000000
#define HD 64
#define NC 16
#define TILE 64
#define PX 68          // padded smem pitch (floats) for [k][n] tiles: conflict-free + float4 aligned
#define NTILES ((NN + TILE - 1) / TILE)

// Scratch (allocation-free rule: __device__ globals)
__device__ float g_agg0[(size_t)NN * HD];   // sum of src features over type==true edges, per dst
__device__ float g_agg1[(size_t)NN * HD];   // type==false
__device__ float g_cnt0[NN];
__device__ float g_cnt1[NN];

// ---------------------------------------------------------------------------
// Edge phase: 16 threads per edge, each thread handles one float4 (64 floats).
// Vector atomics (red.global.add.v4.f32, sm_90+) -> 4x fewer REDG ops.
// ---------------------------------------------------------------------------
__global__ void __launch_bounds__(256) edge_kernel(
    const float* __restrict__ feat,
    const int* __restrict__ src,
    const int* __restrict__ dst,
    const int* __restrict__ et)
{
    int e = blockIdx.x * 16 + (threadIdx.x >> 4);
    if (e >= NE) return;
    int l = threadIdx.x & 15;
    int s = __ldg(src + e);
    int d = __ldg(dst + e);
    int t = __ldg(et + e);
    float4 v = *reinterpret_cast<const float4*>(feat + (size_t)s * HD + l * 4);
    float* p = (t ? g_agg0 : g_agg1) + (size_t)d * HD + l * 4;
    asm volatile("red.global.add.v4.f32 [%0], {%1,%2,%3,%4};"
                 :: "l"(p), "f"(v.x), "f"(v.y), "f"(v.z), "f"(v.w)
                 : "memory");
    if (l == 0) atomicAdd((t ? g_cnt0 : g_cnt1) + d, 1.0f);
}

__device__ __forceinline__ float sigmoidf_(float x) {
    return 1.0f / (1.0f + __expf(-x));
}
__device__ __forceinline__ float tanhf_(float x) {
    return 2.0f / (1.0f + __expf(-2.0f * x)) - 1.0f;
}

// ---------------------------------------------------------------------------
// Node phase: one block = 256 threads, processes tiles of 64 nodes.
// All weights cached in smem (transposed k-major), loaded ONCE per block.
// Thread (ns = tid&15, js = tid>>4) owns a 4-node x 4-output register tile.
// Pipeline per tile (smem-aliased buffers):
//   XA = agg0^T  -> (after GEMM1) Pre^T
//   XB = agg1^T  -> (after GEMM2) H^T
//   XF = feat^T  (live throughout)
// GEMM1: pre = agg0@W0^T + agg1@W1^T + cnt0*b0 + cnt1*b1
// GEMM2 (3 gate slices r,z,n): gi = pre@Wih^T, gh = feat@Whh^T, GRU elementwise
// GEMM3: out = h@Wout^T + bout
// ---------------------------------------------------------------------------
__global__ void __launch_bounds__(256, 1) node_kernel(
    const float* __restrict__ feat,
    const float* __restrict__ W0g, const float* __restrict__ b0g,
    const float* __restrict__ W1g, const float* __restrict__ b1g,
    const float* __restrict__ Wihg, const float* __restrict__ Whhg,
    const float* __restrict__ bihg, const float* __restrict__ bhhg,
    const float* __restrict__ Woutg, const float* __restrict__ boutg,
    float* __restrict__ out)
{
    extern __shared__ float sm[];
    float* W0s = sm;                  // [64k][64j]
    float* W1s = W0s + 4096;
    float* WIs = W1s + 4096;          // [64k][192j]
    float* WHs = WIs + 12288;
    float* WOs = WHs + 12288;         // [64k][16c]
    float* B0s = WOs + 1024;
    float* B1s = B0s + 64;
    float* BIs = B1s + 64;
    float* BHs = BIs + 192;
    float* BOs = BHs + 192;
    float* XA  = BOs + 16;            // [64k][PX]
    float* XB  = XA + TILE * PX;
    float* XF  = XB + TILE * PX;
    float* C0s = XF + TILE * PX;
    float* C1s = C0s + 64;

    const int tid = threadIdx.x;

    // --- Load weights transposed (k-major). Bank-conflict-free STS (j fast). ---
    for (int i = tid; i < 4096; i += 256) {
        int j = i & 63, k = i >> 6;
        W0s[k * 64 + j] = W0g[j * 64 + k];
        W1s[k * 64 + j] = W1g[j * 64 + k];
    }
    for (int i = tid; i < 12288; i += 256) {
        int j = i % 192, k = i / 192;
        WIs[k * 192 + j] = Wihg[j * 64 + k];
        WHs[k * 192 + j] = Whhg[j * 64 + k];
    }
    for (int i = tid; i < 1024; i += 256) {
        int c = i & 15, k = i >> 4;
        WOs[k * 16 + c] = Woutg[c * 64 + k];
    }
    if (tid < 64)  { B0s[tid] = b0g[tid]; B1s[tid] = b1g[tid]; }
    if (tid < 192) { BIs[tid] = bihg[tid]; BHs[tid] = bhhg[tid]; }
    if (tid < 16)  { BOs[tid] = boutg[tid]; }

    const int ns = tid & 15;   // node slot: nodes 4*ns .. 4*ns+3
    const int js = tid >> 4;   // output slot: outputs 4*js .. 4*js+3 (and c=js in GEMM3)

    for (int tile = blockIdx.x; tile < NTILES; tile += gridDim.x) {
        __syncthreads();  // covers weight load (1st iter) + prev-tile buffer reads
        const int base = tile * TILE;

        // --- Stage agg0/agg1/feat transposed into smem ([k][n], pitch PX). ---
        for (int i = tid; i < TILE * 16; i += 256) {
            int k4 = i >> 6, n = i & 63;
            int gn = base + n;
            float4 a0, a1, f;
            if (gn < NN) {
                a0 = *reinterpret_cast<const float4*>(g_agg0 + (size_t)gn * HD + k4 * 4);
                a1 = *reinterpret_cast<const float4*>(g_agg1 + (size_t)gn * HD + k4 * 4);
                f  = *reinterpret_cast<const float4*>(feat   + (size_t)gn * HD + k4 * 4);
            } else {
                a0 = make_float4(0.f, 0.f, 0.f, 0.f); a1 = a0; f = a0;
            }
            int kb = 4 * k4;
            XA[(kb + 0) * PX + n] = a0.x; XA[(kb + 1) * PX + n] = a0.y;
            XA[(kb + 2) * PX + n] = a0.z; XA[(kb + 3) * PX + n] = a0.w;
            XB[(kb + 0) * PX + n] = a1.x; XB[(kb + 1) * PX + n] = a1.y;
            XB[(kb + 2) * PX + n] = a1.z; XB[(kb + 3) * PX + n] = a1.w;
            XF[(kb + 0) * PX + n] = f.x;  XF[(kb + 1) * PX + n] = f.y;
            XF[(kb + 2) * PX + n] = f.z;  XF[(kb + 3) * PX + n] = f.w;
        }
        if (tid < TILE) {
            int gn = base + tid;
            C0s[tid] = (gn < NN) ? g_cnt0[gn] : 0.0f;
            C1s[tid] = (gn < NN) ? g_cnt1[gn] : 0.0f;
        }
        __syncthreads();

        // --- GEMM1: pre[n][j] ---
        float acc[4][4];
        #pragma unroll
        for (int q = 0; q < 4; q++)
            #pragma unroll
            for (int p = 0; p < 4; p++) acc[q][p] = 0.0f;

        #pragma unroll 8
        for (int k = 0; k < 64; k++) {
            float4 x0 = *reinterpret_cast<const float4*>(XA + k * PX + 4 * ns);
            float4 x1 = *reinterpret_cast<const float4*>(XB + k * PX + 4 * ns);
            float4 w0 = *reinterpret_cast<const float4*>(W0s + k * 64 + 4 * js);
            float4 w1 = *reinterpret_cast<const float4*>(W1s + k * 64 + 4 * js);
            const float xq0[4] = {x0.x, x0.y, x0.z, x0.w};
            const float xq1[4] = {x1.x, x1.y, x1.z, x1.w};
            const float wp0[4] = {w0.x, w0.y, w0.z, w0.w};
            const float wp1[4] = {w1.x, w1.y, w1.z, w1.w};
            #pragma unroll
            for (int q = 0; q < 4; q++)
                #pragma unroll
                for (int p = 0; p < 4; p++)
                    acc[q][p] += xq0[q] * wp0[p] + xq1[q] * wp1[p];
        }
        {
            float4 b0v = *reinterpret_cast<const float4*>(B0s + 4 * js);
            float4 b1v = *reinterpret_cast<const float4*>(B1s + 4 * js);
            const float b0p[4] = {b0v.x, b0v.y, b0v.z, b0v.w};
            const float b1p[4] = {b1v.x, b1v.y, b1v.z, b1v.w};
            #pragma unroll
            for (int q = 0; q < 4; q++) {
                float c0 = C0s[4 * ns + q], c1 = C1s[4 * ns + q];
                #pragma unroll
                for (int p = 0; p < 4; p++)
                    acc[q][p] += c0 * b0p[p] + c1 * b1p[p];
            }
        }
        __syncthreads();   // everyone done reading XA/XB as inputs
        // store Pre^T into XA (aliases dead agg0 tile)
        #pragma unroll
        for (int p = 0; p < 4; p++) {
            *reinterpret_cast<float4*>(XA + (4 * js + p) * PX + 4 * ns) =
                make_float4(acc[0][p], acc[1][p], acc[2][p], acc[3][p]);
        }
        __syncthreads();

        // --- GEMM2 + GRU elementwise (3 gate slices; r,z kept in registers) ---
        float rr[4][4], zz[4][4];
        #pragma unroll
        for (int g = 0; g < 3; g++) {
            float gi[4][4], gh[4][4];
            #pragma unroll
            for (int q = 0; q < 4; q++)
                #pragma unroll
                for (int p = 0; p < 4; p++) { gi[q][p] = 0.0f; gh[q][p] = 0.0f; }

            #pragma unroll 8
            for (int k = 0; k < 64; k++) {
                float4 pv = *reinterpret_cast<const float4*>(XA + k * PX + 4 * ns);
                float4 fv = *reinterpret_cast<const float4*>(XF + k * PX + 4 * ns);
                float4 wi = *reinterpret_cast<const float4*>(WIs + k * 192 + g * 64 + 4 * js);
                float4 wh = *reinterpret_cast<const float4*>(WHs + k * 192 + g * 64 + 4 * js);
                const float pq[4] = {pv.x, pv.y, pv.z, pv.w};
                const float fq[4] = {fv.x, fv.y, fv.z, fv.w};
                const float wip[4] = {wi.x, wi.y, wi.z, wi.w};
                const float whp[4] = {wh.x, wh.y, wh.z, wh.w};
                #pragma unroll
                for (int q = 0; q < 4; q++)
                    #pragma unroll
                    for (int p = 0; p < 4; p++) {
                        gi[q][p] += pq[q] * wip[p];
                        gh[q][p] += fq[q] * whp[p];
                    }
            }
            float4 biv = *reinterpret_cast<const float4*>(BIs + g * 64 + 4 * js);
            float4 bhv = *reinterpret_cast<const float4*>(BHs + g * 64 + 4 * js);
            const float bip[4] = {biv.x, biv.y, biv.z, biv.w};
            const float bhp[4] = {bhv.x, bhv.y, bhv.z, bhv.w};

            if (g == 0) {
                #pragma unroll
                for (int q = 0; q < 4; q++)
                    #pragma unroll
                    for (int p = 0; p < 4; p++)
                        rr[q][p] = sigmoidf_(gi[q][p] + bip[p] + gh[q][p] + bhp[p]);
            } else if (g == 1) {
                #pragma unroll
                for (int q = 0; q < 4; q++)
                    #pragma unroll
                    for (int p = 0; p < 4; p++)
                        zz[q][p] = sigmoidf_(gi[q][p] + bip[p] + gh[q][p] + bhp[p]);
            } else {
                // n = tanh(i_n + r * h_n);  h = (1-z)*n + z*feat
                #pragma unroll
                for (int p = 0; p < 4; p++) {
                    float hq[4];
                    #pragma unroll
                    for (int q = 0; q < 4; q++) {
                        float a = gi[q][p] + bip[p];
                        float b = gh[q][p] + bhp[p];
                        float nn = tanhf_(a + rr[q][p] * b);
                        float fv2 = XF[(4 * js + p) * PX + 4 * ns + q];
                        hq[q] = (1.0f - zz[q][p]) * nn + zz[q][p] * fv2;
                    }
                    // store H^T into XB (aliases dead agg1 tile)
                    *reinterpret_cast<float4*>(XB + (4 * js + p) * PX + 4 * ns) =
                        make_float4(hq[0], hq[1], hq[2], hq[3]);
                }
            }
        }
        __syncthreads();

        // --- GEMM3: out[n][c], c = js ---
        float o[4] = {0.f, 0.f, 0.f, 0.f};
        #pragma unroll 8
        for (int k = 0; k < 64; k++) {
            float4 h4 = *reinterpret_cast<const float4*>(XB + k * PX + 4 * ns);
            float w = WOs[k * 16 + js];
            o[0] += h4.x * w; o[1] += h4.y * w; o[2] += h4.z * w; o[3] += h4.w * w;
        }
        float bo = BOs[js];
        #pragma unroll
        for (int q = 0; q < 4; q++) {
            int gn = base + 4 * ns + q;
            if (gn < NN) out[(size_t)gn * NC + js] = o[q] + bo;
        }
    }
}

// ---------------------------------------------------------------------------
extern "C" void kernel_launch(void* const* d_in, const int* in_sizes, int n_in,
                              void* d_out, int out_size)
{
    const float* feat = (const float*)d_in[0];
    const int*   src  = (const int*)d_in[1];
    const int*   dst  = (const int*)d_in[2];
    const int*   et   = (const int*)d_in[3];
    const float* W0   = (const float*)d_in[4];
    const float* b0   = (const float*)d_in[5];
    const float* W1   = (const float*)d_in[6];
    const float* b1   = (const float*)d_in[7];
    const float* Wih  = (const float*)d_in[8];
    const float* Whh  = (const float*)d_in[9];
    const float* bih  = (const float*)d_in[10];
    const float* bhh  = (const float*)d_in[11];
    const float* Wout = (const float*)d_in[12];
    const float* bout = (const float*)d_in[13];
    float* out = (float*)d_out;

    void *p0, *p1, *p2, *p3;
    cudaGetSymbolAddress(&p0, g_agg0);
    cudaGetSymbolAddress(&p1, g_agg1);
    cudaGetSymbolAddress(&p2, g_cnt0);
    cudaGetSymbolAddress(&p3, g_cnt1);
    cudaMemsetAsync(p0, 0, sizeof(float) * (size_t)NN * HD);
    cudaMemsetAsync(p1, 0, sizeof(float) * (size_t)NN * HD);
    cudaMemsetAsync(p2, 0, sizeof(float) * NN);
    cudaMemsetAsync(p3, 0, sizeof(float) * NN);

    edge_kernel<<<(NE + 15) / 16, 256>>>(feat, src, dst, et);

    const int SMEM_BYTES = 47504 * 4;  // 190016 B
    cudaFuncSetAttribute(node_kernel,
                         cudaFuncAttributeMaxDynamicSharedMemorySize, SMEM_BYTES);
    node_kernel<<<148, 256, SMEM_BYTES>>>(feat, W0, b0, W1, b1,
                                          Wih, Whh, bih, bhh, Wout, bout, out);
}